// round 14
// baseline (speedup 1.0000x reference)
#include <cuda_runtime.h>
#include <cuda_fp16.h>
#include <cstdint>
#include <cstddef>

#define N_SRC   100000
#define N_DST   50000
#define NODE_IN 128
#define HID     64
#define NTILE   (N_DST / 8)

// g_P stored PERMUTED per 32-col half: perm_off = half*32 + 8*(lane&3) + 2*nt + b
__device__ __half g_P[(size_t)N_SRC * HID];
__device__ float  g_R[(size_t)N_DST * HID];

// ---------------------------------------------------------------------------
__device__ __forceinline__ uint32_t smem_u32(const void* p) {
    uint32_t a;
    asm("{ .reg .u64 t; cvta.to.shared.u64 t, %1; cvt.u32.u64 %0, t; }" : "=r"(a) : "l"(p));
    return a;
}
__device__ __forceinline__ void ldsm4(uint32_t r[4], uint32_t addr) {
    asm volatile("ldmatrix.sync.aligned.m8n8.x4.shared.b16 {%0,%1,%2,%3}, [%4];"
        : "=r"(r[0]), "=r"(r[1]), "=r"(r[2]), "=r"(r[3]) : "r"(addr));
}
__device__ __forceinline__ void mma_f16(float d[4], const uint32_t a[4],
                                        uint32_t b0, uint32_t b1) {
    asm volatile("mma.sync.aligned.m16n8k16.row.col.f32.f16.f16.f32 "
        "{%0,%1,%2,%3}, {%4,%5,%6,%7}, {%8,%9}, {%0,%1,%2,%3};"
        : "+f"(d[0]), "+f"(d[1]), "+f"(d[2]), "+f"(d[3])
        : "r"(a[0]), "r"(a[1]), "r"(a[2]), "r"(a[3]), "r"(b0), "r"(b1));
}
__device__ __forceinline__ uint32_t h2u(__half2 v) { return *(uint32_t*)&v; }

// 1-pass fp16 GEMM (A single, B single), warp tile 32x32
template<int KSTEPS, int STRIDE>
__device__ __forceinline__ void gemm_1p(uint32_t aS, uint32_t bS,
                                        int mrow, int ncol, int lane,
                                        float acc[2][4][4]) {
    const int arow = mrow + (lane & 15);
    const int asel = (lane >> 4) * 8;
    const int brow = ncol + ((lane >> 4) << 3) + (lane & 7);
    const int bsel = ((lane >> 3) & 1) * 8;
    #pragma unroll
    for (int ks = 0; ks < KSTEPS; ks++) {
        uint32_t ah[2][4], bs[2][4];
        #pragma unroll
        for (int mt = 0; mt < 2; mt++) {
            const uint32_t off = (uint32_t)(((arow + mt * 16) * STRIDE + ks * 16 + asel) * 2);
            ldsm4(ah[mt], aS + off);
        }
        #pragma unroll
        for (int j = 0; j < 2; j++) {
            const uint32_t off = (uint32_t)(((brow + j * 16) * STRIDE + ks * 16 + bsel) * 2);
            ldsm4(bs[j], bS + off);
        }
        #pragma unroll
        for (int mt = 0; mt < 2; mt++)
            #pragma unroll
            for (int nt = 0; nt < 4; nt++) {
                const int j = nt >> 1, hf = (nt & 1) * 2;
                mma_f16(acc[mt][nt], ah[mt], bs[j][hf], bs[j][hf + 1]);
            }
    }
}

// ---------------------------------------------------------------------------
// Kernel 1: P(fp16, permuted) = nf @ Wo_top, R(fp32) = nf[:N_DST] @ Wn_top
// ---------------------------------------------------------------------------
#define POFF_A  0        // 128 x 136 fp16 = 34816 B
#define POFF_W  34816    // 64 x 136 fp16 = 17408 B
#define PJ_SMEM 52224
#define PJ_BLOCKS 296
#define PJ_PSPLIT 197

__global__ __launch_bounds__(256, 2)
void k_projT(const float* __restrict__ nf,
             const float* __restrict__ Wo,
             const float* __restrict__ Wn)
{
    extern __shared__ char smc[];
    const int tid = threadIdx.x, lane = tid & 31, wid = tid >> 5;
    const int mrow = (wid & 3) * 32, ncol = (wid >> 2) * 32;

    const bool isP = (blockIdx.x < PJ_PSPLIT);
    const float* W = isP ? Wo : Wn;
    const int limit = isP ? N_SRC : N_DST;
    const int ntile = (limit + 127) >> 7;
    const int t0 = isP ? blockIdx.x : (blockIdx.x - PJ_PSPLIT);
    const int ts = isP ? PJ_PSPLIT : (PJ_BLOCKS - PJ_PSPLIT);

    for (int i = tid; i < 64 * 128; i += 256) {
        const int n = i >> 7, k = i & 127;
        ((__half*)(smc + POFF_W))[n * 136 + k] = __float2half(W[k * 64 + n]);
    }
    const uint32_t aS = smem_u32(smc + POFF_A);
    const uint32_t bS = smem_u32(smc + POFF_W);

    int tile = t0;
    float4 ev[16];
    if (tile < ntile) {
        const int base = tile * 128;
        #pragma unroll
        for (int t = 0; t < 8; t++) {
            const int idx = tid + 256 * t;
            const int r = idx >> 4, c16 = idx & 15;
            ev[2 * t] = make_float4(0.f, 0.f, 0.f, 0.f);
            ev[2 * t + 1] = ev[2 * t];
            if (base + r < limit) {
                const float4* row = (const float4*)(nf + (size_t)(base + r) * NODE_IN);
                ev[2 * t]     = row[c16 * 2];
                ev[2 * t + 1] = row[c16 * 2 + 1];
            }
        }
    }

    for (; tile < ntile; tile += ts) {
        __syncthreads();
        const int base = tile * 128;
        #pragma unroll
        for (int t = 0; t < 8; t++) {
            const int idx = tid + 256 * t;
            const int r = idx >> 4, c16 = idx & 15;
            const float4 v0 = ev[2 * t], v1 = ev[2 * t + 1];
            uint4 pk;
            pk.x = h2u(__floats2half2_rn(v0.x, v0.y));
            pk.y = h2u(__floats2half2_rn(v0.z, v0.w));
            pk.z = h2u(__floats2half2_rn(v1.x, v1.y));
            pk.w = h2u(__floats2half2_rn(v1.z, v1.w));
            *(uint4*)(smc + POFF_A + (size_t)r * 272 + c16 * 16) = pk;
        }
        __syncthreads();

        float acc[2][4][4];
        #pragma unroll
        for (int a = 0; a < 2; a++)
            #pragma unroll
            for (int b = 0; b < 4; b++)
                #pragma unroll
                for (int c = 0; c < 4; c++) acc[a][b][c] = 0.f;

        gemm_1p<8, 136>(aS, bS, mrow, ncol, lane, acc);

        {
            const int tn = tile + ts;
            if (tn < ntile) {
                const int nbase = tn * 128;
                #pragma unroll
                for (int t = 0; t < 8; t++) {
                    const int idx = tid + 256 * t;
                    const int r = idx >> 4, c16 = idx & 15;
                    ev[2 * t] = make_float4(0.f, 0.f, 0.f, 0.f);
                    ev[2 * t + 1] = ev[2 * t];
                    if (nbase + r < limit) {
                        const float4* row = (const float4*)(nf + (size_t)(nbase + r) * NODE_IN);
                        ev[2 * t]     = row[c16 * 2];
                        ev[2 * t + 1] = row[c16 * 2 + 1];
                    }
                }
            }
        }

        #pragma unroll
        for (int mt = 0; mt < 2; mt++) {
            const int r0 = base + mrow + mt * 16 + (lane >> 2);
            if (isP) {
                const int po = ncol + 8 * (lane & 3);
                uint4 q0, q1;
                q0.x = h2u(__floats2half2_rn(acc[mt][0][0], acc[mt][0][1]));
                q0.y = h2u(__floats2half2_rn(acc[mt][1][0], acc[mt][1][1]));
                q0.z = h2u(__floats2half2_rn(acc[mt][2][0], acc[mt][2][1]));
                q0.w = h2u(__floats2half2_rn(acc[mt][3][0], acc[mt][3][1]));
                q1.x = h2u(__floats2half2_rn(acc[mt][0][2], acc[mt][0][3]));
                q1.y = h2u(__floats2half2_rn(acc[mt][1][2], acc[mt][1][3]));
                q1.z = h2u(__floats2half2_rn(acc[mt][2][2], acc[mt][2][3]));
                q1.w = h2u(__floats2half2_rn(acc[mt][3][2], acc[mt][3][3]));
                if (r0 < limit)
                    *(uint4*)(g_P + (size_t)r0 * HID + po) = q0;
                if (r0 + 8 < limit)
                    *(uint4*)(g_P + (size_t)(r0 + 8) * HID + po) = q1;
            } else {
                #pragma unroll
                for (int nt = 0; nt < 4; nt++) {
                    const int c = ncol + nt * 8 + (lane & 3) * 2;
                    if (r0 < limit)
                        *(float2*)(g_R + (size_t)r0 * HID + c) =
                            make_float2(acc[mt][nt][0], acc[mt][nt][1]);
                    if (r0 + 8 < limit)
                        *(float2*)(g_R + (size_t)(r0 + 8) * HID + c) =
                            make_float2(acc[mt][nt][2], acc[mt][nt][3]);
                }
            }
        }
    }
}

// ---------------------------------------------------------------------------
// Kernel 2: R13 structure + hoisted GEMM2 B-fragments (w2 in registers)
// ---------------------------------------------------------------------------
#define OFF_E    0        // 128 x 72 fp16 = 18432
#define OFF_EO   18432    // e_out buffer   = 18432
#define OFF_W1   36864
#define OFF_W2   46080
#define OFF_W3   55296
#define OFF_HN   64512    // 16 x 72 fp16 (rows 8..15 stay zero)
#define OFF_LOG  66816    // 128 floats
#define OFF_TAU  67328
#define OFF_AMX  67360
#define OFF_V    67392
#define OFF_BE   67648
#define OFF_BO   67904
#define OFF_BN   68160
#define OFF_SRC  68416
#define OFF_C    68928
#define FS_SMEM  68944

__global__ __launch_bounds__(256, 2)
void k_fusedT(const float* __restrict__ ef,
              const int*   __restrict__ src_idx,
              const float* __restrict__ We,  const float* __restrict__ be,
              const float* __restrict__ Wa,  const float* __restrict__ ba,
              const float* __restrict__ wa,
              const float* __restrict__ Wo,  const float* __restrict__ bo,
              const float* __restrict__ Wn,  const float* __restrict__ bn,
              float* __restrict__ out)
{
    extern __shared__ char smc[];
    const int tid = threadIdx.x, lane = tid & 31, wid = tid >> 5;
    const int mrow = (wid & 3) * 32, ncol = (wid >> 2) * 32;

    float* sLog = (float*)(smc + OFF_LOG);
    float* sTau = (float*)(smc + OFF_TAU);
    float* sAmx = (float*)(smc + OFF_AMX);
    float* sV   = (float*)(smc + OFF_V);
    float* sBe  = (float*)(smc + OFF_BE);
    float* sBo  = (float*)(smc + OFF_BO);
    float* sBn  = (float*)(smc + OFF_BN);
    int*   sSrc = (int*)  (smc + OFF_SRC);

    for (int i = tid; i < 4096; i += 256) {
        const int n = i >> 6, k = i & 63;
        ((__half*)(smc + OFF_W1))[n * 72 + k] = __float2half(We[k * 64 + n]);
        ((__half*)(smc + OFF_W2))[n * 72 + k] = __float2half(Wo[(NODE_IN + k) * 64 + n]);
        ((__half*)(smc + OFF_W3))[n * 72 + k] = __float2half(Wn[(NODE_IN + k) * 64 + n]);
    }
    for (int i = tid; i < 288; i += 256)
        ((uint32_t*)(smc + OFF_HN + 1152))[i] = 0;
    if (tid < 64) {
        sBe[tid] = be[tid]; sBo[tid] = bo[tid]; sBn[tid] = bn[tid];
        float sv = 0.f;
        #pragma unroll 8
        for (int k = 0; k < 64; k++) sv = fmaf(Wa[tid * 64 + k], wa[k], sv);
        sV[tid] = sv;
    }
    if (tid == 64) {
        float sc = 0.f;
        for (int k = 0; k < 64; k++) sc = fmaf(ba[k], wa[k], sc);
        *(float*)(smc + OFF_C) = sc;
    }
    __syncthreads();
    const float cval = *(const float*)(smc + OFF_C);

    const uint32_t eS  = smem_u32(smc + OFF_E);
    const uint32_t eoS = smem_u32(smc + OFF_EO);
    const uint32_t w1 = smem_u32(smc + OFF_W1), w2 = smem_u32(smc + OFF_W2);
    const uint32_t w3 = smem_u32(smc + OFF_W3);
    const uint32_t hnS = smem_u32(smc + OFF_HN);

    const int bro  = ((lane >> 4) << 3) + (lane & 7);
    const int bsel = ((lane >> 3) & 1) * 8;

    // hoist GEMM3 B fragments (loop-invariant)
    uint32_t b3[2][4];
    {
        const int nc = wid * 8;
        #pragma unroll
        for (int g = 0; g < 2; g++) {
            const uint32_t off = (uint32_t)(((nc + (lane & 7)) * 72 + (lane >> 3) * 8 + g * 32) * 2);
            ldsm4(b3[g], w3 + off);
        }
    }
    // hoist GEMM2 B fragments (w2, loop-invariant): 32 regs
    uint32_t bw2[4][2][4];
    #pragma unroll
    for (int ks = 0; ks < 4; ks++)
        #pragma unroll
        for (int j = 0; j < 2; j++) {
            const uint32_t off =
                (uint32_t)(((ncol + bro + j * 16) * 72 + ks * 16 + bsel) * 2);
            ldsm4(bw2[ks][j], w2 + off);
        }

    // -------- edge-tile prefetch (registers) --------
    int tile = blockIdx.x;
    float4 ev[8];
    int srcv = 0;
    if (tile < NTILE) {
        const float4* eg = (const float4*)(ef + (size_t)tile * 8192);
        #pragma unroll
        for (int t = 0; t < 4; t++) {
            const int idx = tid + 256 * t;
            const int r = idx >> 3, c8 = idx & 7;
            ev[2 * t]     = eg[r * 16 + c8 * 2];
            ev[2 * t + 1] = eg[r * 16 + c8 * 2 + 1];
        }
        if (tid < 128) srcv = src_idx[tile * 128 + tid];
    }

    for (; tile < NTILE; tile += gridDim.x) {
        // ---- staging from REGISTERS -> fp16 smem + fused logits ----
        #pragma unroll
        for (int t = 0; t < 4; t++) {
            const int idx = tid + 256 * t;
            const int r = idx >> 3, c8 = idx & 7;
            const float4 v0 = ev[2 * t];
            const float4 v1 = ev[2 * t + 1];
            uint4 pk;
            pk.x = h2u(__floats2half2_rn(v0.x, v0.y));
            pk.y = h2u(__floats2half2_rn(v0.z, v0.w));
            pk.z = h2u(__floats2half2_rn(v1.x, v1.y));
            pk.w = h2u(__floats2half2_rn(v1.z, v1.w));
            *(uint4*)(smc + OFF_E + (size_t)r * 144 + c8 * 16) = pk;
            const float* vv = sV + c8 * 8;
            float p = v0.x * vv[0] + v0.y * vv[1] + v0.z * vv[2] + v0.w * vv[3]
                    + v1.x * vv[4] + v1.y * vv[5] + v1.z * vv[6] + v1.w * vv[7];
            p += __shfl_xor_sync(0xffffffffu, p, 1);
            p += __shfl_xor_sync(0xffffffffu, p, 2);
            p += __shfl_xor_sync(0xffffffffu, p, 4);
            if ((tid & 7) == 0) sLog[r] = p;
        }
        if (tid < 128) sSrc[tid] = srcv;
        __syncthreads();   // S1: E + logits + src visible

        // ---- sparsemax (8 threads of warp 0) ----
        if (tid < 8) {
            float z[16], amax = -3.4e38f;
            #pragma unroll
            for (int d = 0; d < 16; d++) {
                float raw = sLog[tid * 16 + d] + cval;
                raw = (raw > 0.f) ? raw : 0.01f * raw;
                sLog[tid * 16 + d] = raw;
                z[d] = raw; amax = fmaxf(amax, z[d]);
            }
            #pragma unroll
            for (int d = 0; d < 16; d++) z[d] -= amax;
            #pragma unroll
            for (int kk2 = 2; kk2 <= 16; kk2 <<= 1)
                #pragma unroll
                for (int j = kk2 >> 1; j > 0; j >>= 1)
                    #pragma unroll
                    for (int i = 0; i < 16; i++) {
                        const int l = i ^ j;
                        if (l > i) {
                            const bool up = ((i & kk2) == 0);
                            const float a0 = z[i], b0 = z[l];
                            if (up ? (a0 > b0) : (a0 < b0)) { z[i] = b0; z[l] = a0; }
                        }
                    }
            float cs = 0.f, cssel = 0.f, kk = 1.f;
            #pragma unroll
            for (int j = 1; j <= 16; j++) {
                const float zz = z[16 - j];
                cs += zz;
                if (1.f + (float)j * zz > cs) { kk = (float)j; cssel = cs; }
            }
            sTau[tid] = (cssel - 1.f) / kk;
            sAmx[tid] = amax;
        }

        // ---- P-row prefetch: permuted layout -> ONE uint4 per row ----
        uint4 pq0[2], pq1[2];
        {
            const int po = ncol + 8 * (lane & 3);
            #pragma unroll
            for (int mt = 0; mt < 2; mt++) {
                const int r0 = mrow + mt * 16 + (lane >> 2);
                pq0[mt] = *(const uint4*)(g_P + (size_t)sSrc[r0] * HID + po);
                pq1[mt] = *(const uint4*)(g_P + (size_t)sSrc[r0 + 8] * HID + po);
            }
        }

        float acc[2][4][4];

        // ---- GEMM1: e_out_pre = E @ We^T ----
        #pragma unroll
        for (int a = 0; a < 2; a++)
            #pragma unroll
            for (int b = 0; b < 4; b++)
                #pragma unroll
                for (int c = 0; c < 4; c++) acc[a][b][c] = 0.f;
        gemm_1p<4, 72>(eS, w1, mrow, ncol, lane, acc);

        // ---- epilogue1: relu(+be) -> e_out buffer ----
        #pragma unroll
        for (int mt = 0; mt < 2; mt++) {
            const int r0 = mrow + mt * 16 + (lane >> 2);
            #pragma unroll
            for (int nt = 0; nt < 4; nt++) {
                const int c = ncol + nt * 8 + (lane & 3) * 2;
                const float x0 = fmaxf(acc[mt][nt][0] + sBe[c],     0.f);
                const float x1 = fmaxf(acc[mt][nt][1] + sBe[c + 1], 0.f);
                const float x2 = fmaxf(acc[mt][nt][2] + sBe[c],     0.f);
                const float x3 = fmaxf(acc[mt][nt][3] + sBe[c + 1], 0.f);
                *(uint32_t*)(smc + OFF_EO + (size_t)(r0 * 72 + c) * 2) =
                    h2u(__floats2half2_rn(x0, x1));
                *(uint32_t*)(smc + OFF_EO + (size_t)((r0 + 8) * 72 + c) * 2) =
                    h2u(__floats2half2_rn(x2, x3));
            }
        }
        __syncthreads();   // S2: e_out + tau visible

        // ---- GEMM2: m_pre = e_out @ Wo_bot^T  (B from registers) ----
        #pragma unroll
        for (int a = 0; a < 2; a++)
            #pragma unroll
            for (int b = 0; b < 4; b++)
                #pragma unroll
                for (int c = 0; c < 4; c++) acc[a][b][c] = 0.f;
        {
            const int arow = mrow + (lane & 15);
            const int asel = (lane >> 4) * 8;
            #pragma unroll
            for (int ks = 0; ks < 4; ks++) {
                uint32_t ah[2][4];
                #pragma unroll
                for (int mt = 0; mt < 2; mt++) {
                    const uint32_t off =
                        (uint32_t)(((arow + mt * 16) * 72 + ks * 16 + asel) * 2);
                    ldsm4(ah[mt], eoS + off);
                }
                #pragma unroll
                for (int mt = 0; mt < 2; mt++)
                    #pragma unroll
                    for (int nt = 0; nt < 4; nt++) {
                        const int j = nt >> 1, hf = (nt & 1) * 2;
                        mma_f16(acc[mt][nt], ah[mt], bw2[ks][j][hf], bw2[ks][j][hf + 1]);
                    }
            }
        }

        // ---- epilogue2: m = relu(acc + P + bo); alpha-weighted sum -> HN ----
        #pragma unroll
        for (int mt = 0; mt < 2; mt++) {
            const int ln = (mrow >> 4) + mt;
            const int r0 = mrow + mt * 16 + (lane >> 2);
            const int r1 = r0 + 8;
            const float at = sAmx[ln] + sTau[ln];
            const float al0 = fmaxf(sLog[r0] - at, 0.f);
            const float al1 = fmaxf(sLog[r1] - at, 0.f);
            const uint32_t* q0 = (const uint32_t*)&pq0[mt];
            const uint32_t* q1 = (const uint32_t*)&pq1[mt];
            #pragma unroll
            for (int nt = 0; nt < 4; nt++) {
                const int c = ncol + nt * 8 + (lane & 3) * 2;
                const float2 p0 = __half22float2(*(const __half2*)&q0[nt]);
                const float2 p1 = __half22float2(*(const __half2*)&q1[nt]);
                const float m00 = fmaxf(acc[mt][nt][0] + p0.x + sBo[c],     0.f);
                const float m01 = fmaxf(acc[mt][nt][1] + p0.y + sBo[c + 1], 0.f);
                const float m10 = fmaxf(acc[mt][nt][2] + p1.x + sBo[c],     0.f);
                const float m11 = fmaxf(acc[mt][nt][3] + p1.y + sBo[c + 1], 0.f);
                float sx = m00 * al0 + m10 * al1;
                float sy = m01 * al0 + m11 * al1;
                sx += __shfl_xor_sync(0xffffffffu, sx, 4);
                sy += __shfl_xor_sync(0xffffffffu, sy, 4);
                sx += __shfl_xor_sync(0xffffffffu, sx, 8);
                sy += __shfl_xor_sync(0xffffffffu, sy, 8);
                sx += __shfl_xor_sync(0xffffffffu, sx, 16);
                sy += __shfl_xor_sync(0xffffffffu, sy, 16);
                if (lane < 4)
                    *(uint32_t*)(smc + OFF_HN + (size_t)(ln * 72 + c) * 2) =
                        h2u(__floats2half2_rn(sx, sy));
            }
        }
        __syncthreads();   // S3: HN visible

        // ---- prefetch NEXT tile (overlaps GEMM3 + out stores) ----
        {
            const int tnext = tile + gridDim.x;
            if (tnext < NTILE) {
                const float4* eg = (const float4*)(ef + (size_t)tnext * 8192);
                #pragma unroll
                for (int t = 0; t < 4; t++) {
                    const int idx = tid + 256 * t;
                    const int r = idx >> 3, c8 = idx & 7;
                    ev[2 * t]     = eg[r * 16 + c8 * 2];
                    ev[2 * t + 1] = eg[r * 16 + c8 * 2 + 1];
                }
                if (tid < 128) srcv = src_idx[tnext * 128 + tid];
            }
        }

        // ---- GEMM3 (M=16 padded, 1-pass): out = relu(R + HN @ Wn_bot^T + bn) ----
        {
            float acc3[4] = {0.f, 0.f, 0.f, 0.f};
            #pragma unroll
            for (int ks = 0; ks < 4; ks++) {
                uint32_t a3[4];
                const uint32_t aoff = (uint32_t)(((lane & 15) * 72 + ks * 16 + (lane >> 4) * 8) * 2);
                ldsm4(a3, hnS + aoff);
                const int g = ks >> 1, pr = (ks & 1) * 2;
                mma_f16(acc3, a3, b3[g][pr], b3[g][pr + 1]);
            }
            const int node = tile * 8 + (lane >> 2);
            const int col = wid * 8 + (lane & 3) * 2;
            const float2 r2 = *(const float2*)(g_R + (size_t)node * HID + col);
            const float o0 = acc3[0] + r2.x + sBn[col];
            const float o1 = acc3[1] + r2.y + sBn[col + 1];
            *(float2*)(out + (size_t)node * HID + col) =
                make_float2(fmaxf(o0, 0.f), fmaxf(o1, 0.f));
        }
        // no trailing sync (same hazard argument as R9/R12/R13)
    }
}

// ---------------------------------------------------------------------------
extern "C" void kernel_launch(void* const* d_in, const int* in_sizes, int n_in,
                              void* d_out, int out_size)
{
    const float* nf = (const float*)d_in[0];
    const float* ef = (const float*)d_in[1];
    const int*   si = (const int*)  d_in[2];
    const float* We = (const float*)d_in[3];
    const float* be = (const float*)d_in[4];
    const float* Wa = (const float*)d_in[5];
    const float* ba = (const float*)d_in[6];
    const float* wa = (const float*)d_in[7];
    const float* Wo = (const float*)d_in[8];
    const float* bo = (const float*)d_in[9];
    const float* Wn = (const float*)d_in[10];
    const float* bn = (const float*)d_in[11];
    float* out = (float*)d_out;

    cudaFuncSetAttribute(k_projT,  cudaFuncAttributeMaxDynamicSharedMemorySize, PJ_SMEM);
    cudaFuncSetAttribute(k_fusedT, cudaFuncAttributeMaxDynamicSharedMemorySize, FS_SMEM);

    k_projT<<<PJ_BLOCKS, 256, PJ_SMEM>>>(nf, Wo, Wn);
    k_fusedT<<<296, 256, FS_SMEM>>>(ef, si, We, be, Wa, ba, wa, Wo, bo, Wn, bn, out);
}

// round 15
// speedup vs baseline: 1.0171x; 1.0171x over previous
#include <cuda_runtime.h>
#include <cuda_fp16.h>
#include <cstdint>
#include <cstddef>

#define N_SRC   100000
#define N_DST   50000
#define NODE_IN 128
#define HID     64
#define NTILE   (N_DST / 8)

// g_P stored PERMUTED per 32-col half: perm_off = half*32 + 8*(lane&3) + 2*nt + b
__device__ __half g_P[(size_t)N_SRC * HID];
__device__ float  g_R[(size_t)N_DST * HID];

// ---------------------------------------------------------------------------
__device__ __forceinline__ uint32_t smem_u32(const void* p) {
    uint32_t a;
    asm("{ .reg .u64 t; cvta.to.shared.u64 t, %1; cvt.u32.u64 %0, t; }" : "=r"(a) : "l"(p));
    return a;
}
__device__ __forceinline__ void ldsm4(uint32_t r[4], uint32_t addr) {
    asm volatile("ldmatrix.sync.aligned.m8n8.x4.shared.b16 {%0,%1,%2,%3}, [%4];"
        : "=r"(r[0]), "=r"(r[1]), "=r"(r[2]), "=r"(r[3]) : "r"(addr));
}
__device__ __forceinline__ void mma_f16(float d[4], const uint32_t a[4],
                                        uint32_t b0, uint32_t b1) {
    asm volatile("mma.sync.aligned.m16n8k16.row.col.f32.f16.f16.f32 "
        "{%0,%1,%2,%3}, {%4,%5,%6,%7}, {%8,%9}, {%0,%1,%2,%3};"
        : "+f"(d[0]), "+f"(d[1]), "+f"(d[2]), "+f"(d[3])
        : "r"(a[0]), "r"(a[1]), "r"(a[2]), "r"(a[3]), "r"(b0), "r"(b1));
}
__device__ __forceinline__ uint32_t h2u(__half2 v) { return *(uint32_t*)&v; }

// 1-pass fp16 GEMM (A single, B single), warp tile 32x32
template<int KSTEPS, int STRIDE>
__device__ __forceinline__ void gemm_1p(uint32_t aS, uint32_t bS,
                                        int mrow, int ncol, int lane,
                                        float acc[2][4][4]) {
    const int arow = mrow + (lane & 15);
    const int asel = (lane >> 4) * 8;
    const int brow = ncol + ((lane >> 4) << 3) + (lane & 7);
    const int bsel = ((lane >> 3) & 1) * 8;
    #pragma unroll
    for (int ks = 0; ks < KSTEPS; ks++) {
        uint32_t ah[2][4], bs[2][4];
        #pragma unroll
        for (int mt = 0; mt < 2; mt++) {
            const uint32_t off = (uint32_t)(((arow + mt * 16) * STRIDE + ks * 16 + asel) * 2);
            ldsm4(ah[mt], aS + off);
        }
        #pragma unroll
        for (int j = 0; j < 2; j++) {
            const uint32_t off = (uint32_t)(((brow + j * 16) * STRIDE + ks * 16 + bsel) * 2);
            ldsm4(bs[j], bS + off);
        }
        #pragma unroll
        for (int mt = 0; mt < 2; mt++)
            #pragma unroll
            for (int nt = 0; nt < 4; nt++) {
                const int j = nt >> 1, hf = (nt & 1) * 2;
                mma_f16(acc[mt][nt], ah[mt], bs[j][hf], bs[j][hf + 1]);
            }
    }
}

// ---------------------------------------------------------------------------
// Kernel 1: P(fp16, permuted) = nf @ Wo_top, R(fp32) = nf[:N_DST] @ Wn_top
//           (identical to R13)
// ---------------------------------------------------------------------------
#define POFF_A  0        // 128 x 136 fp16 = 34816 B
#define POFF_W  34816    // 64 x 136 fp16 = 17408 B
#define PJ_SMEM 52224
#define PJ_BLOCKS 296
#define PJ_PSPLIT 197

__global__ __launch_bounds__(256, 2)
void k_projT(const float* __restrict__ nf,
             const float* __restrict__ Wo,
             const float* __restrict__ Wn)
{
    extern __shared__ char smc[];
    const int tid = threadIdx.x, lane = tid & 31, wid = tid >> 5;
    const int mrow = (wid & 3) * 32, ncol = (wid >> 2) * 32;

    const bool isP = (blockIdx.x < PJ_PSPLIT);
    const float* W = isP ? Wo : Wn;
    const int limit = isP ? N_SRC : N_DST;
    const int ntile = (limit + 127) >> 7;
    const int t0 = isP ? blockIdx.x : (blockIdx.x - PJ_PSPLIT);
    const int ts = isP ? PJ_PSPLIT : (PJ_BLOCKS - PJ_PSPLIT);

    for (int i = tid; i < 64 * 128; i += 256) {
        const int n = i >> 7, k = i & 127;
        ((__half*)(smc + POFF_W))[n * 136 + k] = __float2half(W[k * 64 + n]);
    }
    const uint32_t aS = smem_u32(smc + POFF_A);
    const uint32_t bS = smem_u32(smc + POFF_W);

    int tile = t0;
    float4 ev[16];
    if (tile < ntile) {
        const int base = tile * 128;
        #pragma unroll
        for (int t = 0; t < 8; t++) {
            const int idx = tid + 256 * t;
            const int r = idx >> 4, c16 = idx & 15;
            ev[2 * t] = make_float4(0.f, 0.f, 0.f, 0.f);
            ev[2 * t + 1] = ev[2 * t];
            if (base + r < limit) {
                const float4* row = (const float4*)(nf + (size_t)(base + r) * NODE_IN);
                ev[2 * t]     = row[c16 * 2];
                ev[2 * t + 1] = row[c16 * 2 + 1];
            }
        }
    }

    for (; tile < ntile; tile += ts) {
        __syncthreads();
        const int base = tile * 128;
        #pragma unroll
        for (int t = 0; t < 8; t++) {
            const int idx = tid + 256 * t;
            const int r = idx >> 4, c16 = idx & 15;
            const float4 v0 = ev[2 * t], v1 = ev[2 * t + 1];
            uint4 pk;
            pk.x = h2u(__floats2half2_rn(v0.x, v0.y));
            pk.y = h2u(__floats2half2_rn(v0.z, v0.w));
            pk.z = h2u(__floats2half2_rn(v1.x, v1.y));
            pk.w = h2u(__floats2half2_rn(v1.z, v1.w));
            *(uint4*)(smc + POFF_A + (size_t)r * 272 + c16 * 16) = pk;
        }
        __syncthreads();

        float acc[2][4][4];
        #pragma unroll
        for (int a = 0; a < 2; a++)
            #pragma unroll
            for (int b = 0; b < 4; b++)
                #pragma unroll
                for (int c = 0; c < 4; c++) acc[a][b][c] = 0.f;

        gemm_1p<8, 136>(aS, bS, mrow, ncol, lane, acc);

        {
            const int tn = tile + ts;
            if (tn < ntile) {
                const int nbase = tn * 128;
                #pragma unroll
                for (int t = 0; t < 8; t++) {
                    const int idx = tid + 256 * t;
                    const int r = idx >> 4, c16 = idx & 15;
                    ev[2 * t] = make_float4(0.f, 0.f, 0.f, 0.f);
                    ev[2 * t + 1] = ev[2 * t];
                    if (nbase + r < limit) {
                        const float4* row = (const float4*)(nf + (size_t)(nbase + r) * NODE_IN);
                        ev[2 * t]     = row[c16 * 2];
                        ev[2 * t + 1] = row[c16 * 2 + 1];
                    }
                }
            }
        }

        #pragma unroll
        for (int mt = 0; mt < 2; mt++) {
            const int r0 = base + mrow + mt * 16 + (lane >> 2);
            if (isP) {
                const int po = ncol + 8 * (lane & 3);
                uint4 q0, q1;
                q0.x = h2u(__floats2half2_rn(acc[mt][0][0], acc[mt][0][1]));
                q0.y = h2u(__floats2half2_rn(acc[mt][1][0], acc[mt][1][1]));
                q0.z = h2u(__floats2half2_rn(acc[mt][2][0], acc[mt][2][1]));
                q0.w = h2u(__floats2half2_rn(acc[mt][3][0], acc[mt][3][1]));
                q1.x = h2u(__floats2half2_rn(acc[mt][0][2], acc[mt][0][3]));
                q1.y = h2u(__floats2half2_rn(acc[mt][1][2], acc[mt][1][3]));
                q1.z = h2u(__floats2half2_rn(acc[mt][2][2], acc[mt][2][3]));
                q1.w = h2u(__floats2half2_rn(acc[mt][3][2], acc[mt][3][3]));
                if (r0 < limit)
                    *(uint4*)(g_P + (size_t)r0 * HID + po) = q0;
                if (r0 + 8 < limit)
                    *(uint4*)(g_P + (size_t)(r0 + 8) * HID + po) = q1;
            } else {
                #pragma unroll
                for (int nt = 0; nt < 4; nt++) {
                    const int c = ncol + nt * 8 + (lane & 3) * 2;
                    if (r0 < limit)
                        *(float2*)(g_R + (size_t)r0 * HID + c) =
                            make_float2(acc[mt][nt][0], acc[mt][nt][1]);
                    if (r0 + 8 < limit)
                        *(float2*)(g_R + (size_t)(r0 + 8) * HID + c) =
                            make_float2(acc[mt][nt][2], acc[mt][nt][3]);
                }
            }
        }
    }
}

// ---------------------------------------------------------------------------
// Kernel 2: R13 + fragment-native e_out exchange
//   EO2 layout: [mr(4)][khalf(2)][mt(2)][lane(32)][ksl(2)] x uint4 (16 KB)
//   producer lane == consumer lane (chaining identity); STS.128 / LDS.128
// ---------------------------------------------------------------------------
#define OFF_E    0        // 128 x 72 fp16 = 18432
#define OFF_EO   18432    // 16384 (fragment-native e_out)
#define OFF_W1   36864
#define OFF_W2   46080
#define OFF_W3   55296
#define OFF_HN   64512    // 16 x 72 fp16 (rows 8..15 stay zero)
#define OFF_LOG  66816    // 128 floats
#define OFF_TAU  67328
#define OFF_AMX  67360
#define OFF_V    67392
#define OFF_BE   67648
#define OFF_BO   67904
#define OFF_BN   68160
#define OFF_SRC  68416
#define OFF_C    68928
#define FS_SMEM  68944

// byte offset inside EO2
__device__ __forceinline__ uint32_t eo2_off(int mr, int khalf, int mt, int lane, int ksl) {
    return (uint32_t)(((((mr * 2 + khalf) * 2 + mt) * 32 + lane) * 2 + ksl) * 16);
}

__global__ __launch_bounds__(256, 2)
void k_fusedT(const float* __restrict__ ef,
              const int*   __restrict__ src_idx,
              const float* __restrict__ We,  const float* __restrict__ be,
              const float* __restrict__ Wa,  const float* __restrict__ ba,
              const float* __restrict__ wa,
              const float* __restrict__ Wo,  const float* __restrict__ bo,
              const float* __restrict__ Wn,  const float* __restrict__ bn,
              float* __restrict__ out)
{
    extern __shared__ char smc[];
    const int tid = threadIdx.x, lane = tid & 31, wid = tid >> 5;
    const int mrow = (wid & 3) * 32, ncol = (wid >> 2) * 32;
    const int mr = wid & 3;           // M-group 0..3
    const int myhalf = wid >> 2;      // k-half this warp produces

    float* sLog = (float*)(smc + OFF_LOG);
    float* sTau = (float*)(smc + OFF_TAU);
    float* sAmx = (float*)(smc + OFF_AMX);
    float* sV   = (float*)(smc + OFF_V);
    float* sBe  = (float*)(smc + OFF_BE);
    float* sBo  = (float*)(smc + OFF_BO);
    float* sBn  = (float*)(smc + OFF_BN);
    int*   sSrc = (int*)  (smc + OFF_SRC);

    for (int i = tid; i < 4096; i += 256) {
        const int n = i >> 6, k = i & 63;
        ((__half*)(smc + OFF_W1))[n * 72 + k] = __float2half(We[k * 64 + n]);
        ((__half*)(smc + OFF_W2))[n * 72 + k] = __float2half(Wo[(NODE_IN + k) * 64 + n]);
        ((__half*)(smc + OFF_W3))[n * 72 + k] = __float2half(Wn[(NODE_IN + k) * 64 + n]);
    }
    for (int i = tid; i < 288; i += 256)
        ((uint32_t*)(smc + OFF_HN + 1152))[i] = 0;
    if (tid < 64) {
        sBe[tid] = be[tid]; sBo[tid] = bo[tid]; sBn[tid] = bn[tid];
        float sv = 0.f;
        #pragma unroll 8
        for (int k = 0; k < 64; k++) sv = fmaf(Wa[tid * 64 + k], wa[k], sv);
        sV[tid] = sv;
    }
    if (tid == 64) {
        float sc = 0.f;
        for (int k = 0; k < 64; k++) sc = fmaf(ba[k], wa[k], sc);
        *(float*)(smc + OFF_C) = sc;
    }
    __syncthreads();
    const float cval = *(const float*)(smc + OFF_C);

    const uint32_t eS  = smem_u32(smc + OFF_E);
    const uint32_t eoS = smem_u32(smc + OFF_EO);
    const uint32_t w1 = smem_u32(smc + OFF_W1), w2 = smem_u32(smc + OFF_W2);
    const uint32_t w3 = smem_u32(smc + OFF_W3);
    const uint32_t hnS = smem_u32(smc + OFF_HN);

    const int bro  = ((lane >> 4) << 3) + (lane & 7);
    const int bsel = ((lane >> 3) & 1) * 8;

    // hoist GEMM3 B fragments (loop-invariant)
    uint32_t b3[2][4];
    {
        const int nc = wid * 8;
        #pragma unroll
        for (int g = 0; g < 2; g++) {
            const uint32_t off = (uint32_t)(((nc + (lane & 7)) * 72 + (lane >> 3) * 8 + g * 32) * 2);
            ldsm4(b3[g], w3 + off);
        }
    }

    // -------- edge-tile prefetch (registers) --------
    int tile = blockIdx.x;
    float4 ev[8];
    int srcv = 0;
    if (tile < NTILE) {
        const float4* eg = (const float4*)(ef + (size_t)tile * 8192);
        #pragma unroll
        for (int t = 0; t < 4; t++) {
            const int idx = tid + 256 * t;
            const int r = idx >> 3, c8 = idx & 7;
            ev[2 * t]     = eg[r * 16 + c8 * 2];
            ev[2 * t + 1] = eg[r * 16 + c8 * 2 + 1];
        }
        if (tid < 128) srcv = src_idx[tile * 128 + tid];
    }

    for (; tile < NTILE; tile += gridDim.x) {
        // ---- staging from REGISTERS -> fp16 smem + fused logits ----
        #pragma unroll
        for (int t = 0; t < 4; t++) {
            const int idx = tid + 256 * t;
            const int r = idx >> 3, c8 = idx & 7;
            const float4 v0 = ev[2 * t];
            const float4 v1 = ev[2 * t + 1];
            uint4 pk;
            pk.x = h2u(__floats2half2_rn(v0.x, v0.y));
            pk.y = h2u(__floats2half2_rn(v0.z, v0.w));
            pk.z = h2u(__floats2half2_rn(v1.x, v1.y));
            pk.w = h2u(__floats2half2_rn(v1.z, v1.w));
            *(uint4*)(smc + OFF_E + (size_t)r * 144 + c8 * 16) = pk;
            const float* vv = sV + c8 * 8;
            float p = v0.x * vv[0] + v0.y * vv[1] + v0.z * vv[2] + v0.w * vv[3]
                    + v1.x * vv[4] + v1.y * vv[5] + v1.z * vv[6] + v1.w * vv[7];
            p += __shfl_xor_sync(0xffffffffu, p, 1);
            p += __shfl_xor_sync(0xffffffffu, p, 2);
            p += __shfl_xor_sync(0xffffffffu, p, 4);
            if ((tid & 7) == 0) sLog[r] = p;
        }
        if (tid < 128) sSrc[tid] = srcv;
        __syncthreads();   // S1: E + logits + src visible

        // ---- sparsemax (8 threads of warp 0) ----
        if (tid < 8) {
            float z[16], amax = -3.4e38f;
            #pragma unroll
            for (int d = 0; d < 16; d++) {
                float raw = sLog[tid * 16 + d] + cval;
                raw = (raw > 0.f) ? raw : 0.01f * raw;
                sLog[tid * 16 + d] = raw;
                z[d] = raw; amax = fmaxf(amax, z[d]);
            }
            #pragma unroll
            for (int d = 0; d < 16; d++) z[d] -= amax;
            #pragma unroll
            for (int kk2 = 2; kk2 <= 16; kk2 <<= 1)
                #pragma unroll
                for (int j = kk2 >> 1; j > 0; j >>= 1)
                    #pragma unroll
                    for (int i = 0; i < 16; i++) {
                        const int l = i ^ j;
                        if (l > i) {
                            const bool up = ((i & kk2) == 0);
                            const float a0 = z[i], b0 = z[l];
                            if (up ? (a0 > b0) : (a0 < b0)) { z[i] = b0; z[l] = a0; }
                        }
                    }
            float cs = 0.f, cssel = 0.f, kk = 1.f;
            #pragma unroll
            for (int j = 1; j <= 16; j++) {
                const float zz = z[16 - j];
                cs += zz;
                if (1.f + (float)j * zz > cs) { kk = (float)j; cssel = cs; }
            }
            sTau[tid] = (cssel - 1.f) / kk;
            sAmx[tid] = amax;
        }

        // ---- P-row prefetch: permuted layout -> ONE uint4 per row ----
        uint4 pq0[2], pq1[2];
        {
            const int po = ncol + 8 * (lane & 3);
            #pragma unroll
            for (int mt = 0; mt < 2; mt++) {
                const int r0 = mrow + mt * 16 + (lane >> 2);
                pq0[mt] = *(const uint4*)(g_P + (size_t)sSrc[r0] * HID + po);
                pq1[mt] = *(const uint4*)(g_P + (size_t)sSrc[r0 + 8] * HID + po);
            }
        }

        float acc[2][4][4];

        // ---- GEMM1: e_out_pre = E @ We^T ----
        #pragma unroll
        for (int a = 0; a < 2; a++)
            #pragma unroll
            for (int b = 0; b < 4; b++)
                #pragma unroll
                for (int c = 0; c < 4; c++) acc[a][b][c] = 0.f;
        gemm_1p<4, 72>(eS, w1, mrow, ncol, lane, acc);

        // ---- epilogue1: relu(+be) -> fragment-native EO2 (4 x STS.128) ----
        #pragma unroll
        for (int mt = 0; mt < 2; mt++) {
            #pragma unroll
            for (int ksl = 0; ksl < 2; ksl++) {
                const int c0 = ncol + (2 * ksl) * 8 + (lane & 3) * 2;
                const int c1 = c0 + 8;
                uint4 q;
                q.x = h2u(__floats2half2_rn(
                    fmaxf(acc[mt][2 * ksl][0] + sBe[c0],     0.f),
                    fmaxf(acc[mt][2 * ksl][1] + sBe[c0 + 1], 0.f)));
                q.y = h2u(__floats2half2_rn(
                    fmaxf(acc[mt][2 * ksl][2] + sBe[c0],     0.f),
                    fmaxf(acc[mt][2 * ksl][3] + sBe[c0 + 1], 0.f)));
                q.z = h2u(__floats2half2_rn(
                    fmaxf(acc[mt][2 * ksl + 1][0] + sBe[c1],     0.f),
                    fmaxf(acc[mt][2 * ksl + 1][1] + sBe[c1 + 1], 0.f)));
                q.w = h2u(__floats2half2_rn(
                    fmaxf(acc[mt][2 * ksl + 1][2] + sBe[c1],     0.f),
                    fmaxf(acc[mt][2 * ksl + 1][3] + sBe[c1 + 1], 0.f)));
                *(uint4*)(smc + OFF_EO + eo2_off(mr, myhalf, mt, lane, ksl)) = q;
            }
        }
        __syncthreads();   // S2: e_out fragments + tau visible

        // ---- GEMM2: m_pre = e_out @ Wo_bot^T (A via LDS.128, B via ldsm) ----
        #pragma unroll
        for (int a = 0; a < 2; a++)
            #pragma unroll
            for (int b = 0; b < 4; b++)
                #pragma unroll
                for (int c = 0; c < 4; c++) acc[a][b][c] = 0.f;
        #pragma unroll
        for (int ks = 0; ks < 4; ks++) {
            const int khalf = ks >> 1, ksl = ks & 1;
            uint32_t bs[2][4];
            #pragma unroll
            for (int j = 0; j < 2; j++) {
                const uint32_t off =
                    (uint32_t)(((ncol + bro + j * 16) * 72 + ks * 16 + bsel) * 2);
                ldsm4(bs[j], w2 + off);
            }
            #pragma unroll
            for (int mt = 0; mt < 2; mt++) {
                const uint4 aq = *(const uint4*)(smc + OFF_EO +
                                                 eo2_off(mr, khalf, mt, lane, ksl));
                const uint32_t ah[4] = {aq.x, aq.y, aq.z, aq.w};
                #pragma unroll
                for (int nt = 0; nt < 4; nt++) {
                    const int j = nt >> 1, hf = (nt & 1) * 2;
                    mma_f16(acc[mt][nt], ah, bs[j][hf], bs[j][hf + 1]);
                }
            }
        }

        // ---- epilogue2: m = relu(acc + P + bo); alpha-weighted sum -> HN ----
        #pragma unroll
        for (int mt = 0; mt < 2; mt++) {
            const int ln = (mrow >> 4) + mt;
            const int r0 = mrow + mt * 16 + (lane >> 2);
            const int r1 = r0 + 8;
            const float at = sAmx[ln] + sTau[ln];
            const float al0 = fmaxf(sLog[r0] - at, 0.f);
            const float al1 = fmaxf(sLog[r1] - at, 0.f);
            const uint32_t* q0 = (const uint32_t*)&pq0[mt];
            const uint32_t* q1 = (const uint32_t*)&pq1[mt];
            #pragma unroll
            for (int nt = 0; nt < 4; nt++) {
                const int c = ncol + nt * 8 + (lane & 3) * 2;
                const float2 p0 = __half22float2(*(const __half2*)&q0[nt]);
                const float2 p1 = __half22float2(*(const __half2*)&q1[nt]);
                const float m00 = fmaxf(acc[mt][nt][0] + p0.x + sBo[c],     0.f);
                const float m01 = fmaxf(acc[mt][nt][1] + p0.y + sBo[c + 1], 0.f);
                const float m10 = fmaxf(acc[mt][nt][2] + p1.x + sBo[c],     0.f);
                const float m11 = fmaxf(acc[mt][nt][3] + p1.y + sBo[c + 1], 0.f);
                float sx = m00 * al0 + m10 * al1;
                float sy = m01 * al0 + m11 * al1;
                sx += __shfl_xor_sync(0xffffffffu, sx, 4);
                sy += __shfl_xor_sync(0xffffffffu, sy, 4);
                sx += __shfl_xor_sync(0xffffffffu, sx, 8);
                sy += __shfl_xor_sync(0xffffffffu, sy, 8);
                sx += __shfl_xor_sync(0xffffffffu, sx, 16);
                sy += __shfl_xor_sync(0xffffffffu, sy, 16);
                if (lane < 4)
                    *(uint32_t*)(smc + OFF_HN + (size_t)(ln * 72 + c) * 2) =
                        h2u(__floats2half2_rn(sx, sy));
            }
        }
        __syncthreads();   // S3: HN visible

        // ---- prefetch NEXT tile (overlaps GEMM3 + out stores) ----
        {
            const int tnext = tile + gridDim.x;
            if (tnext < NTILE) {
                const float4* eg = (const float4*)(ef + (size_t)tnext * 8192);
                #pragma unroll
                for (int t = 0; t < 4; t++) {
                    const int idx = tid + 256 * t;
                    const int r = idx >> 3, c8 = idx & 7;
                    ev[2 * t]     = eg[r * 16 + c8 * 2];
                    ev[2 * t + 1] = eg[r * 16 + c8 * 2 + 1];
                }
                if (tid < 128) srcv = src_idx[tnext * 128 + tid];
            }
        }

        // ---- GEMM3 (M=16 padded, 1-pass): out = relu(R + HN @ Wn_bot^T + bn) ----
        {
            float acc3[4] = {0.f, 0.f, 0.f, 0.f};
            #pragma unroll
            for (int ks = 0; ks < 4; ks++) {
                uint32_t a3[4];
                const uint32_t aoff = (uint32_t)(((lane & 15) * 72 + ks * 16 + (lane >> 4) * 8) * 2);
                ldsm4(a3, hnS + aoff);
                const int g = ks >> 1, pr = (ks & 1) * 2;
                mma_f16(acc3, a3, b3[g][pr], b3[g][pr + 1]);
            }
            const int node = tile * 8 + (lane >> 2);
            const int col = wid * 8 + (lane & 3) * 2;
            const float2 r2 = *(const float2*)(g_R + (size_t)node * HID + col);
            const float o0 = acc3[0] + r2.x + sBn[col];
            const float o1 = acc3[1] + r2.y + sBn[col + 1];
            *(float2*)(out + (size_t)node * HID + col) =
                make_float2(fmaxf(o0, 0.f), fmaxf(o1, 0.f));
        }
        // no trailing sync (same hazard argument as R9/R12/R13)
    }
}

// ---------------------------------------------------------------------------
extern "C" void kernel_launch(void* const* d_in, const int* in_sizes, int n_in,
                              void* d_out, int out_size)
{
    const float* nf = (const float*)d_in[0];
    const float* ef = (const float*)d_in[1];
    const int*   si = (const int*)  d_in[2];
    const float* We = (const float*)d_in[3];
    const float* be = (const float*)d_in[4];
    const float* Wa = (const float*)d_in[5];
    const float* ba = (const float*)d_in[6];
    const float* wa = (const float*)d_in[7];
    const float* Wo = (const float*)d_in[8];
    const float* bo = (const float*)d_in[9];
    const float* Wn = (const float*)d_in[10];
    const float* bn = (const float*)d_in[11];
    float* out = (float*)d_out;

    cudaFuncSetAttribute(k_projT,  cudaFuncAttributeMaxDynamicSharedMemorySize, PJ_SMEM);
    cudaFuncSetAttribute(k_fusedT, cudaFuncAttributeMaxDynamicSharedMemorySize, FS_SMEM);

    k_projT<<<PJ_BLOCKS, 256, PJ_SMEM>>>(nf, Wo, Wn);
    k_fusedT<<<296, 256, FS_SMEM>>>(ef, si, We, be, Wa, ba, wa, Wo, bo, Wn, bn, out);
}

// round 16
// speedup vs baseline: 1.0606x; 1.0428x over previous
#include <cuda_runtime.h>
#include <cuda_fp16.h>
#include <cstdint>
#include <cstddef>

#define N_SRC   100000
#define N_DST   50000
#define NODE_IN 128
#define HID     64
#define NTILE   (N_DST / 8)

// g_P stored PERMUTED per 32-col half: perm_off = half*32 + 8*(lane&3) + 2*nt + b
__device__ __half g_P[(size_t)N_SRC * HID];
__device__ float  g_R[(size_t)N_DST * HID];

// ---------------------------------------------------------------------------
__device__ __forceinline__ uint32_t smem_u32(const void* p) {
    uint32_t a;
    asm("{ .reg .u64 t; cvta.to.shared.u64 t, %1; cvt.u32.u64 %0, t; }" : "=r"(a) : "l"(p));
    return a;
}
__device__ __forceinline__ void ldsm4(uint32_t r[4], uint32_t addr) {
    asm volatile("ldmatrix.sync.aligned.m8n8.x4.shared.b16 {%0,%1,%2,%3}, [%4];"
        : "=r"(r[0]), "=r"(r[1]), "=r"(r[2]), "=r"(r[3]) : "r"(addr));
}
__device__ __forceinline__ void mma_f16(float d[4], const uint32_t a[4],
                                        uint32_t b0, uint32_t b1) {
    asm volatile("mma.sync.aligned.m16n8k16.row.col.f32.f16.f16.f32 "
        "{%0,%1,%2,%3}, {%4,%5,%6,%7}, {%8,%9}, {%0,%1,%2,%3};"
        : "+f"(d[0]), "+f"(d[1]), "+f"(d[2]), "+f"(d[3])
        : "r"(a[0]), "r"(a[1]), "r"(a[2]), "r"(a[3]), "r"(b0), "r"(b1));
}
__device__ __forceinline__ uint32_t h2u(__half2 v) { return *(uint32_t*)&v; }

// 1-pass fp16 GEMM (A single, B single), warp tile 32x32
template<int KSTEPS, int STRIDE>
__device__ __forceinline__ void gemm_1p(uint32_t aS, uint32_t bS,
                                        int mrow, int ncol, int lane,
                                        float acc[2][4][4]) {
    const int arow = mrow + (lane & 15);
    const int asel = (lane >> 4) * 8;
    const int brow = ncol + ((lane >> 4) << 3) + (lane & 7);
    const int bsel = ((lane >> 3) & 1) * 8;
    #pragma unroll
    for (int ks = 0; ks < KSTEPS; ks++) {
        uint32_t ah[2][4], bs[2][4];
        #pragma unroll
        for (int mt = 0; mt < 2; mt++) {
            const uint32_t off = (uint32_t)(((arow + mt * 16) * STRIDE + ks * 16 + asel) * 2);
            ldsm4(ah[mt], aS + off);
        }
        #pragma unroll
        for (int j = 0; j < 2; j++) {
            const uint32_t off = (uint32_t)(((brow + j * 16) * STRIDE + ks * 16 + bsel) * 2);
            ldsm4(bs[j], bS + off);
        }
        #pragma unroll
        for (int mt = 0; mt < 2; mt++)
            #pragma unroll
            for (int nt = 0; nt < 4; nt++) {
                const int j = nt >> 1, hf = (nt & 1) * 2;
                mma_f16(acc[mt][nt], ah[mt], bs[j][hf], bs[j][hf + 1]);
            }
    }
}

// ---------------------------------------------------------------------------
// Kernel 1: P(fp16, permuted) = nf @ Wo_top, R(fp32) = nf[:N_DST] @ Wn_top
//           (identical to R13)
// ---------------------------------------------------------------------------
#define POFF_A  0        // 128 x 136 fp16 = 34816 B
#define POFF_W  34816    // 64 x 136 fp16 = 17408 B
#define PJ_SMEM 52224
#define PJ_BLOCKS 296
#define PJ_PSPLIT 197

__global__ __launch_bounds__(256, 2)
void k_projT(const float* __restrict__ nf,
             const float* __restrict__ Wo,
             const float* __restrict__ Wn)
{
    extern __shared__ char smc[];
    const int tid = threadIdx.x, lane = tid & 31, wid = tid >> 5;
    const int mrow = (wid & 3) * 32, ncol = (wid >> 2) * 32;

    const bool isP = (blockIdx.x < PJ_PSPLIT);
    const float* W = isP ? Wo : Wn;
    const int limit = isP ? N_SRC : N_DST;
    const int ntile = (limit + 127) >> 7;
    const int t0 = isP ? blockIdx.x : (blockIdx.x - PJ_PSPLIT);
    const int ts = isP ? PJ_PSPLIT : (PJ_BLOCKS - PJ_PSPLIT);

    for (int i = tid; i < 64 * 128; i += 256) {
        const int n = i >> 7, k = i & 127;
        ((__half*)(smc + POFF_W))[n * 136 + k] = __float2half(W[k * 64 + n]);
    }
    const uint32_t aS = smem_u32(smc + POFF_A);
    const uint32_t bS = smem_u32(smc + POFF_W);

    int tile = t0;
    float4 ev[16];
    if (tile < ntile) {
        const int base = tile * 128;
        #pragma unroll
        for (int t = 0; t < 8; t++) {
            const int idx = tid + 256 * t;
            const int r = idx >> 4, c16 = idx & 15;
            ev[2 * t] = make_float4(0.f, 0.f, 0.f, 0.f);
            ev[2 * t + 1] = ev[2 * t];
            if (base + r < limit) {
                const float4* row = (const float4*)(nf + (size_t)(base + r) * NODE_IN);
                ev[2 * t]     = row[c16 * 2];
                ev[2 * t + 1] = row[c16 * 2 + 1];
            }
        }
    }

    for (; tile < ntile; tile += ts) {
        __syncthreads();
        const int base = tile * 128;
        #pragma unroll
        for (int t = 0; t < 8; t++) {
            const int idx = tid + 256 * t;
            const int r = idx >> 4, c16 = idx & 15;
            const float4 v0 = ev[2 * t], v1 = ev[2 * t + 1];
            uint4 pk;
            pk.x = h2u(__floats2half2_rn(v0.x, v0.y));
            pk.y = h2u(__floats2half2_rn(v0.z, v0.w));
            pk.z = h2u(__floats2half2_rn(v1.x, v1.y));
            pk.w = h2u(__floats2half2_rn(v1.z, v1.w));
            *(uint4*)(smc + POFF_A + (size_t)r * 272 + c16 * 16) = pk;
        }
        __syncthreads();

        float acc[2][4][4];
        #pragma unroll
        for (int a = 0; a < 2; a++)
            #pragma unroll
            for (int b = 0; b < 4; b++)
                #pragma unroll
                for (int c = 0; c < 4; c++) acc[a][b][c] = 0.f;

        gemm_1p<8, 136>(aS, bS, mrow, ncol, lane, acc);

        {
            const int tn = tile + ts;
            if (tn < ntile) {
                const int nbase = tn * 128;
                #pragma unroll
                for (int t = 0; t < 8; t++) {
                    const int idx = tid + 256 * t;
                    const int r = idx >> 4, c16 = idx & 15;
                    ev[2 * t] = make_float4(0.f, 0.f, 0.f, 0.f);
                    ev[2 * t + 1] = ev[2 * t];
                    if (nbase + r < limit) {
                        const float4* row = (const float4*)(nf + (size_t)(nbase + r) * NODE_IN);
                        ev[2 * t]     = row[c16 * 2];
                        ev[2 * t + 1] = row[c16 * 2 + 1];
                    }
                }
            }
        }

        #pragma unroll
        for (int mt = 0; mt < 2; mt++) {
            const int r0 = base + mrow + mt * 16 + (lane >> 2);
            if (isP) {
                const int po = ncol + 8 * (lane & 3);
                uint4 q0, q1;
                q0.x = h2u(__floats2half2_rn(acc[mt][0][0], acc[mt][0][1]));
                q0.y = h2u(__floats2half2_rn(acc[mt][1][0], acc[mt][1][1]));
                q0.z = h2u(__floats2half2_rn(acc[mt][2][0], acc[mt][2][1]));
                q0.w = h2u(__floats2half2_rn(acc[mt][3][0], acc[mt][3][1]));
                q1.x = h2u(__floats2half2_rn(acc[mt][0][2], acc[mt][0][3]));
                q1.y = h2u(__floats2half2_rn(acc[mt][1][2], acc[mt][1][3]));
                q1.z = h2u(__floats2half2_rn(acc[mt][2][2], acc[mt][2][3]));
                q1.w = h2u(__floats2half2_rn(acc[mt][3][2], acc[mt][3][3]));
                if (r0 < limit)
                    *(uint4*)(g_P + (size_t)r0 * HID + po) = q0;
                if (r0 + 8 < limit)
                    *(uint4*)(g_P + (size_t)(r0 + 8) * HID + po) = q1;
            } else {
                #pragma unroll
                for (int nt = 0; nt < 4; nt++) {
                    const int c = ncol + nt * 8 + (lane & 3) * 2;
                    if (r0 < limit)
                        *(float2*)(g_R + (size_t)r0 * HID + c) =
                            make_float2(acc[mt][nt][0], acc[mt][nt][1]);
                    if (r0 + 8 < limit)
                        *(float2*)(g_R + (size_t)(r0 + 8) * HID + c) =
                            make_float2(acc[mt][nt][2], acc[mt][nt][3]);
                }
            }
        }
    }
}

// ---------------------------------------------------------------------------
// Kernel 2: R13 + fragment-native e_out exchange, CONFLICT-FREE layout
//   EO2: [mr(4)][khalf(2)][mt(2)][ksl(2)][lane(32)] x uint4 (16 KB)
//   each (mt,ksl) access = 32 lanes x 16B contiguous -> 4 wavefronts
// ---------------------------------------------------------------------------
#define OFF_E    0        // 128 x 72 fp16 = 18432
#define OFF_EO   18432    // 16384 (fragment-native e_out)
#define OFF_W1   36864
#define OFF_W2   46080
#define OFF_W3   55296
#define OFF_HN   64512    // 16 x 72 fp16 (rows 8..15 stay zero)
#define OFF_LOG  66816    // 128 floats
#define OFF_TAU  67328
#define OFF_AMX  67360
#define OFF_V    67392
#define OFF_BE   67648
#define OFF_BO   67904
#define OFF_BN   68160
#define OFF_SRC  68416
#define OFF_C    68928
#define FS_SMEM  68944

// byte offset inside EO2: lanes contiguous (innermost)
__device__ __forceinline__ uint32_t eo2_off(int mr, int khalf, int mt, int ksl, int lane) {
    return (uint32_t)(((((mr * 2 + khalf) * 2 + mt) * 2 + ksl) * 32 + lane) * 16);
}

__global__ __launch_bounds__(256, 2)
void k_fusedT(const float* __restrict__ ef,
              const int*   __restrict__ src_idx,
              const float* __restrict__ We,  const float* __restrict__ be,
              const float* __restrict__ Wa,  const float* __restrict__ ba,
              const float* __restrict__ wa,
              const float* __restrict__ Wo,  const float* __restrict__ bo,
              const float* __restrict__ Wn,  const float* __restrict__ bn,
              float* __restrict__ out)
{
    extern __shared__ char smc[];
    const int tid = threadIdx.x, lane = tid & 31, wid = tid >> 5;
    const int mrow = (wid & 3) * 32, ncol = (wid >> 2) * 32;
    const int mr = wid & 3;           // M-group 0..3
    const int myhalf = wid >> 2;      // k-half this warp produces

    float* sLog = (float*)(smc + OFF_LOG);
    float* sTau = (float*)(smc + OFF_TAU);
    float* sAmx = (float*)(smc + OFF_AMX);
    float* sV   = (float*)(smc + OFF_V);
    float* sBe  = (float*)(smc + OFF_BE);
    float* sBo  = (float*)(smc + OFF_BO);
    float* sBn  = (float*)(smc + OFF_BN);
    int*   sSrc = (int*)  (smc + OFF_SRC);

    for (int i = tid; i < 4096; i += 256) {
        const int n = i >> 6, k = i & 63;
        ((__half*)(smc + OFF_W1))[n * 72 + k] = __float2half(We[k * 64 + n]);
        ((__half*)(smc + OFF_W2))[n * 72 + k] = __float2half(Wo[(NODE_IN + k) * 64 + n]);
        ((__half*)(smc + OFF_W3))[n * 72 + k] = __float2half(Wn[(NODE_IN + k) * 64 + n]);
    }
    for (int i = tid; i < 288; i += 256)
        ((uint32_t*)(smc + OFF_HN + 1152))[i] = 0;
    if (tid < 64) {
        sBe[tid] = be[tid]; sBo[tid] = bo[tid]; sBn[tid] = bn[tid];
        float sv = 0.f;
        #pragma unroll 8
        for (int k = 0; k < 64; k++) sv = fmaf(Wa[tid * 64 + k], wa[k], sv);
        sV[tid] = sv;
    }
    if (tid == 64) {
        float sc = 0.f;
        for (int k = 0; k < 64; k++) sc = fmaf(ba[k], wa[k], sc);
        *(float*)(smc + OFF_C) = sc;
    }
    __syncthreads();
    const float cval = *(const float*)(smc + OFF_C);

    const uint32_t eS  = smem_u32(smc + OFF_E);
    const uint32_t w1 = smem_u32(smc + OFF_W1), w2 = smem_u32(smc + OFF_W2);
    const uint32_t w3 = smem_u32(smc + OFF_W3);
    const uint32_t hnS = smem_u32(smc + OFF_HN);

    const int bro  = ((lane >> 4) << 3) + (lane & 7);
    const int bsel = ((lane >> 3) & 1) * 8;

    // hoist GEMM3 B fragments (loop-invariant)
    uint32_t b3[2][4];
    {
        const int nc = wid * 8;
        #pragma unroll
        for (int g = 0; g < 2; g++) {
            const uint32_t off = (uint32_t)(((nc + (lane & 7)) * 72 + (lane >> 3) * 8 + g * 32) * 2);
            ldsm4(b3[g], w3 + off);
        }
    }

    // -------- edge-tile prefetch (registers) --------
    int tile = blockIdx.x;
    float4 ev[8];
    int srcv = 0;
    if (tile < NTILE) {
        const float4* eg = (const float4*)(ef + (size_t)tile * 8192);
        #pragma unroll
        for (int t = 0; t < 4; t++) {
            const int idx = tid + 256 * t;
            const int r = idx >> 3, c8 = idx & 7;
            ev[2 * t]     = eg[r * 16 + c8 * 2];
            ev[2 * t + 1] = eg[r * 16 + c8 * 2 + 1];
        }
        if (tid < 128) srcv = src_idx[tile * 128 + tid];
    }

    for (; tile < NTILE; tile += gridDim.x) {
        // ---- staging from REGISTERS -> fp16 smem + fused logits ----
        #pragma unroll
        for (int t = 0; t < 4; t++) {
            const int idx = tid + 256 * t;
            const int r = idx >> 3, c8 = idx & 7;
            const float4 v0 = ev[2 * t];
            const float4 v1 = ev[2 * t + 1];
            uint4 pk;
            pk.x = h2u(__floats2half2_rn(v0.x, v0.y));
            pk.y = h2u(__floats2half2_rn(v0.z, v0.w));
            pk.z = h2u(__floats2half2_rn(v1.x, v1.y));
            pk.w = h2u(__floats2half2_rn(v1.z, v1.w));
            *(uint4*)(smc + OFF_E + (size_t)r * 144 + c8 * 16) = pk;
            const float* vv = sV + c8 * 8;
            float p = v0.x * vv[0] + v0.y * vv[1] + v0.z * vv[2] + v0.w * vv[3]
                    + v1.x * vv[4] + v1.y * vv[5] + v1.z * vv[6] + v1.w * vv[7];
            p += __shfl_xor_sync(0xffffffffu, p, 1);
            p += __shfl_xor_sync(0xffffffffu, p, 2);
            p += __shfl_xor_sync(0xffffffffu, p, 4);
            if ((tid & 7) == 0) sLog[r] = p;
        }
        if (tid < 128) sSrc[tid] = srcv;
        __syncthreads();   // S1: E + logits + src visible

        // ---- sparsemax (8 threads of warp 0) ----
        if (tid < 8) {
            float z[16], amax = -3.4e38f;
            #pragma unroll
            for (int d = 0; d < 16; d++) {
                float raw = sLog[tid * 16 + d] + cval;
                raw = (raw > 0.f) ? raw : 0.01f * raw;
                sLog[tid * 16 + d] = raw;
                z[d] = raw; amax = fmaxf(amax, z[d]);
            }
            #pragma unroll
            for (int d = 0; d < 16; d++) z[d] -= amax;
            #pragma unroll
            for (int kk2 = 2; kk2 <= 16; kk2 <<= 1)
                #pragma unroll
                for (int j = kk2 >> 1; j > 0; j >>= 1)
                    #pragma unroll
                    for (int i = 0; i < 16; i++) {
                        const int l = i ^ j;
                        if (l > i) {
                            const bool up = ((i & kk2) == 0);
                            const float a0 = z[i], b0 = z[l];
                            if (up ? (a0 > b0) : (a0 < b0)) { z[i] = b0; z[l] = a0; }
                        }
                    }
            float cs = 0.f, cssel = 0.f, kk = 1.f;
            #pragma unroll
            for (int j = 1; j <= 16; j++) {
                const float zz = z[16 - j];
                cs += zz;
                if (1.f + (float)j * zz > cs) { kk = (float)j; cssel = cs; }
            }
            sTau[tid] = (cssel - 1.f) / kk;
            sAmx[tid] = amax;
        }

        // ---- P-row prefetch: permuted layout -> ONE uint4 per row ----
        uint4 pq0[2], pq1[2];
        {
            const int po = ncol + 8 * (lane & 3);
            #pragma unroll
            for (int mt = 0; mt < 2; mt++) {
                const int r0 = mrow + mt * 16 + (lane >> 2);
                pq0[mt] = *(const uint4*)(g_P + (size_t)sSrc[r0] * HID + po);
                pq1[mt] = *(const uint4*)(g_P + (size_t)sSrc[r0 + 8] * HID + po);
            }
        }

        float acc[2][4][4];

        // ---- GEMM1: e_out_pre = E @ We^T ----
        #pragma unroll
        for (int a = 0; a < 2; a++)
            #pragma unroll
            for (int b = 0; b < 4; b++)
                #pragma unroll
                for (int c = 0; c < 4; c++) acc[a][b][c] = 0.f;
        gemm_1p<4, 72>(eS, w1, mrow, ncol, lane, acc);

        // ---- epilogue1: relu(+be) -> fragment-native EO2 (4 x STS.128,
        //      contiguous per warp access) ----
        #pragma unroll
        for (int mt = 0; mt < 2; mt++) {
            #pragma unroll
            for (int ksl = 0; ksl < 2; ksl++) {
                const int c0 = ncol + (2 * ksl) * 8 + (lane & 3) * 2;
                const int c1 = c0 + 8;
                uint4 q;
                q.x = h2u(__floats2half2_rn(
                    fmaxf(acc[mt][2 * ksl][0] + sBe[c0],     0.f),
                    fmaxf(acc[mt][2 * ksl][1] + sBe[c0 + 1], 0.f)));
                q.y = h2u(__floats2half2_rn(
                    fmaxf(acc[mt][2 * ksl][2] + sBe[c0],     0.f),
                    fmaxf(acc[mt][2 * ksl][3] + sBe[c0 + 1], 0.f)));
                q.z = h2u(__floats2half2_rn(
                    fmaxf(acc[mt][2 * ksl + 1][0] + sBe[c1],     0.f),
                    fmaxf(acc[mt][2 * ksl + 1][1] + sBe[c1 + 1], 0.f)));
                q.w = h2u(__floats2half2_rn(
                    fmaxf(acc[mt][2 * ksl + 1][2] + sBe[c1],     0.f),
                    fmaxf(acc[mt][2 * ksl + 1][3] + sBe[c1 + 1], 0.f)));
                *(uint4*)(smc + OFF_EO + eo2_off(mr, myhalf, mt, ksl, lane)) = q;
            }
        }
        __syncthreads();   // S2: e_out fragments + tau visible

        // ---- GEMM2: m_pre = e_out @ Wo_bot^T (A via LDS.128, B via ldsm) ----
        #pragma unroll
        for (int a = 0; a < 2; a++)
            #pragma unroll
            for (int b = 0; b < 4; b++)
                #pragma unroll
                for (int c = 0; c < 4; c++) acc[a][b][c] = 0.f;
        #pragma unroll
        for (int ks = 0; ks < 4; ks++) {
            const int khalf = ks >> 1, ksl = ks & 1;
            uint32_t bs[2][4];
            #pragma unroll
            for (int j = 0; j < 2; j++) {
                const uint32_t off =
                    (uint32_t)(((ncol + bro + j * 16) * 72 + ks * 16 + bsel) * 2);
                ldsm4(bs[j], w2 + off);
            }
            #pragma unroll
            for (int mt = 0; mt < 2; mt++) {
                const uint4 aq = *(const uint4*)(smc + OFF_EO +
                                                 eo2_off(mr, khalf, mt, ksl, lane));
                const uint32_t ah[4] = {aq.x, aq.y, aq.z, aq.w};
                #pragma unroll
                for (int nt = 0; nt < 4; nt++) {
                    const int j = nt >> 1, hf = (nt & 1) * 2;
                    mma_f16(acc[mt][nt], ah, bs[j][hf], bs[j][hf + 1]);
                }
            }
        }

        // ---- epilogue2: m = relu(acc + P + bo); alpha-weighted sum -> HN ----
        #pragma unroll
        for (int mt = 0; mt < 2; mt++) {
            const int ln = (mrow >> 4) + mt;
            const int r0 = mrow + mt * 16 + (lane >> 2);
            const int r1 = r0 + 8;
            const float at = sAmx[ln] + sTau[ln];
            const float al0 = fmaxf(sLog[r0] - at, 0.f);
            const float al1 = fmaxf(sLog[r1] - at, 0.f);
            const uint32_t* q0 = (const uint32_t*)&pq0[mt];
            const uint32_t* q1 = (const uint32_t*)&pq1[mt];
            #pragma unroll
            for (int nt = 0; nt < 4; nt++) {
                const int c = ncol + nt * 8 + (lane & 3) * 2;
                const float2 p0 = __half22float2(*(const __half2*)&q0[nt]);
                const float2 p1 = __half22float2(*(const __half2*)&q1[nt]);
                const float m00 = fmaxf(acc[mt][nt][0] + p0.x + sBo[c],     0.f);
                const float m01 = fmaxf(acc[mt][nt][1] + p0.y + sBo[c + 1], 0.f);
                const float m10 = fmaxf(acc[mt][nt][2] + p1.x + sBo[c],     0.f);
                const float m11 = fmaxf(acc[mt][nt][3] + p1.y + sBo[c + 1], 0.f);
                float sx = m00 * al0 + m10 * al1;
                float sy = m01 * al0 + m11 * al1;
                sx += __shfl_xor_sync(0xffffffffu, sx, 4);
                sy += __shfl_xor_sync(0xffffffffu, sy, 4);
                sx += __shfl_xor_sync(0xffffffffu, sx, 8);
                sy += __shfl_xor_sync(0xffffffffu, sy, 8);
                sx += __shfl_xor_sync(0xffffffffu, sx, 16);
                sy += __shfl_xor_sync(0xffffffffu, sy, 16);
                if (lane < 4)
                    *(uint32_t*)(smc + OFF_HN + (size_t)(ln * 72 + c) * 2) =
                        h2u(__floats2half2_rn(sx, sy));
            }
        }
        __syncthreads();   // S3: HN visible

        // ---- prefetch NEXT tile (overlaps GEMM3 + out stores) ----
        {
            const int tnext = tile + gridDim.x;
            if (tnext < NTILE) {
                const float4* eg = (const float4*)(ef + (size_t)tnext * 8192);
                #pragma unroll
                for (int t = 0; t < 4; t++) {
                    const int idx = tid + 256 * t;
                    const int r = idx >> 3, c8 = idx & 7;
                    ev[2 * t]     = eg[r * 16 + c8 * 2];
                    ev[2 * t + 1] = eg[r * 16 + c8 * 2 + 1];
                }
                if (tid < 128) srcv = src_idx[tnext * 128 + tid];
            }
        }

        // ---- GEMM3 (M=16 padded, 1-pass): out = relu(R + HN @ Wn_bot^T + bn) ----
        {
            float acc3[4] = {0.f, 0.f, 0.f, 0.f};
            #pragma unroll
            for (int ks = 0; ks < 4; ks++) {
                uint32_t a3[4];
                const uint32_t aoff = (uint32_t)(((lane & 15) * 72 + ks * 16 + (lane >> 4) * 8) * 2);
                ldsm4(a3, hnS + aoff);
                const int g = ks >> 1, pr = (ks & 1) * 2;
                mma_f16(acc3, a3, b3[g][pr], b3[g][pr + 1]);
            }
            const int node = tile * 8 + (lane >> 2);
            const int col = wid * 8 + (lane & 3) * 2;
            const float2 r2 = *(const float2*)(g_R + (size_t)node * HID + col);
            const float o0 = acc3[0] + r2.x + sBn[col];
            const float o1 = acc3[1] + r2.y + sBn[col + 1];
            *(float2*)(out + (size_t)node * HID + col) =
                make_float2(fmaxf(o0, 0.f), fmaxf(o1, 0.f));
        }
        // no trailing sync (same hazard argument as R9/R12/R13)
    }
}

// ---------------------------------------------------------------------------
extern "C" void kernel_launch(void* const* d_in, const int* in_sizes, int n_in,
                              void* d_out, int out_size)
{
    const float* nf = (const float*)d_in[0];
    const float* ef = (const float*)d_in[1];
    const int*   si = (const int*)  d_in[2];
    const float* We = (const float*)d_in[3];
    const float* be = (const float*)d_in[4];
    const float* Wa = (const float*)d_in[5];
    const float* ba = (const float*)d_in[6];
    const float* wa = (const float*)d_in[7];
    const float* Wo = (const float*)d_in[8];
    const float* bo = (const float*)d_in[9];
    const float* Wn = (const float*)d_in[10];
    const float* bn = (const float*)d_in[11];
    float* out = (float*)d_out;

    cudaFuncSetAttribute(k_projT,  cudaFuncAttributeMaxDynamicSharedMemorySize, PJ_SMEM);
    cudaFuncSetAttribute(k_fusedT, cudaFuncAttributeMaxDynamicSharedMemorySize, FS_SMEM);

    k_projT<<<PJ_BLOCKS, 256, PJ_SMEM>>>(nf, Wo, Wn);
    k_fusedT<<<296, 256, FS_SMEM>>>(ef, si, We, be, Wa, ba, wa, Wo, bo, Wn, bn, out);
}